// round 3
// baseline (speedup 1.0000x reference)
#include <cuda_runtime.h>

#define TEXD   1024
#define TEXP   1025          // conv output spatial dim (1024 + 4 - 4 + 1)
#define OUTC   16
#define INC    32
#define TILE   32
#define HALO   35            // TILE + 3
#define CHUNK  8             // input channels per smem chunk

// Scratch (device globals — no allocation allowed)
__device__ float g_filt[INC * 16 * OUTC];          // [i][ky*4+kx][o]
__device__ float g_tex[TEXP * TEXP * OUTC];        // [y][x][o]  (channel-last!)

// ---------------------------------------------------------------------------
// Kernel 1: MLP 76 -> 128 -> 64 -> 8192, tanh, reorder filter to [i][t][o]
// ---------------------------------------------------------------------------
__global__ void mlp_kernel(const float* __restrict__ expr,
                           const float* __restrict__ W1, const float* __restrict__ b1,
                           const float* __restrict__ W2, const float* __restrict__ b2,
                           const float* __restrict__ W3, const float* __restrict__ b3)
{
    __shared__ float sx[76];
    __shared__ float h1[128];
    __shared__ float h2[64];
    const int tid = threadIdx.x;

    if (tid < 76) sx[tid] = expr[tid];
    __syncthreads();

    if (tid < 128) {
        float a = b1[tid];
        const float* w = W1 + tid * 76;
        #pragma unroll 4
        for (int k = 0; k < 76; ++k) a = fmaf(w[k], sx[k], a);
        h1[tid] = (a >= 0.f) ? a : 0.02f * a;
    }
    __syncthreads();

    if (tid < 64) {
        float a = b2[tid];
        const float* w = W2 + tid * 128;
        #pragma unroll 4
        for (int k = 0; k < 128; ++k) a = fmaf(w[k], h1[k], a);
        h2[tid] = (a >= 0.f) ? a : 0.02f * a;
    }
    __syncthreads();

    // f[m], m = o*512 + i*16 + t  (t = ky*4+kx); store as g_filt[(i*16+t)*16 + o]
    for (int m = tid; m < OUTC * INC * 16; m += blockDim.x) {
        float a = b3[m];
        const float* w = W3 + m * 64;
        #pragma unroll 4
        for (int k = 0; k < 64; ++k) a = fmaf(w[k], h2[k], a);
        a = tanhf(a);
        int o = m >> 9;          // m / 512
        int r = m & 511;         // i*16 + t
        g_filt[r * OUTC + o] = a;
    }
}

// ---------------------------------------------------------------------------
// Kernel 2: conv 32ch -> 16ch, 4x4, pad 2, output 1025x1025 channel-last
// block = 256 threads, tile 32x32 outputs, thread = 4 px (x-quad) x 16 outs
// ---------------------------------------------------------------------------
__global__ void __launch_bounds__(256, 2)
conv_kernel(const float* __restrict__ data)
{
    __shared__ float sdata[CHUNK * HALO * HALO];   // 9800 f = 38.3 KB
    __shared__ float sfilt[CHUNK * 16 * OUTC];     // 2048 f =  8.0 KB

    const int tid = threadIdx.x;
    const int q   = tid & 7;        // x-quad 0..7
    const int ty  = tid >> 3;       // row 0..31
    const int x0  = blockIdx.x * TILE;
    const int y0  = blockIdx.y * TILE;

    float acc[4][16];
    #pragma unroll
    for (int p = 0; p < 4; ++p)
        #pragma unroll
        for (int o = 0; o < 16; ++o) acc[p][o] = 0.f;

    for (int c = 0; c < INC / CHUNK; ++c) {
        // ---- load filter chunk ----
        #pragma unroll
        for (int j = tid; j < CHUNK * 16 * OUTC; j += 256)
            sfilt[j] = g_filt[c * (CHUNK * 16 * OUTC) + j];

        // ---- load data chunk (zero-padded halo) ----
        for (int idx = tid; idx < CHUNK * HALO * HALO; idx += 256) {
            int i   = idx / (HALO * HALO);
            int rem = idx - i * (HALO * HALO);
            int r   = rem / HALO;
            int cc  = rem - r * HALO;
            int gy  = y0 - 2 + r;
            int gx  = x0 - 2 + cc;
            float v = 0.f;
            if ((unsigned)gy < 1024u && (unsigned)gx < 1024u) {
                int ci = (c << 3) + i;
                v = data[(ci << 20) + (gy << 10) + gx];
            }
            sdata[idx] = v;
        }
        __syncthreads();

        #pragma unroll 1
        for (int i = 0; i < CHUNK; ++i) {
            #pragma unroll
            for (int ky = 0; ky < 4; ++ky) {
                const float* drow = &sdata[i * (HALO * HALO) + (ty + ky) * HALO + 4 * q];
                float d[7];
                #pragma unroll
                for (int t = 0; t < 7; ++t) d[t] = drow[t];

                #pragma unroll
                for (int kx = 0; kx < 4; ++kx) {
                    const float4* w4 = (const float4*)&sfilt[((i * 4 + ky) * 4 + kx) * OUTC];
                    float ws[16];
                    *(float4*)&ws[0]  = w4[0];
                    *(float4*)&ws[4]  = w4[1];
                    *(float4*)&ws[8]  = w4[2];
                    *(float4*)&ws[12] = w4[3];
                    #pragma unroll
                    for (int p = 0; p < 4; ++p) {
                        float dv = d[p + kx];
                        #pragma unroll
                        for (int o = 0; o < 16; ++o)
                            acc[p][o] = fmaf(dv, ws[o], acc[p][o]);
                    }
                }
            }
        }
        __syncthreads();
    }

    // ---- store channel-last ----
    const int oy = y0 + ty;
    if (oy < TEXP) {
        #pragma unroll
        for (int p = 0; p < 4; ++p) {
            int ox = x0 + 4 * q + p;
            if (ox < TEXP) {
                float4* dst = (float4*)&g_tex[(oy * TEXP + ox) * OUTC];
                dst[0] = make_float4(acc[p][0],  acc[p][1],  acc[p][2],  acc[p][3]);
                dst[1] = make_float4(acc[p][4],  acc[p][5],  acc[p][6],  acc[p][7]);
                dst[2] = make_float4(acc[p][8],  acc[p][9],  acc[p][10], acc[p][11]);
                dst[3] = make_float4(acc[p][12], acc[p][13], acc[p][14], acc[p][15]);
            }
        }
    }
}

// ---------------------------------------------------------------------------
// Kernel 3: bilinear grid sample (border padding, align_corners=False)
// ---------------------------------------------------------------------------
__global__ void sample_kernel(const float* __restrict__ uv, float* __restrict__ out)
{
    int p = blockIdx.x * blockDim.x + threadIdx.x;
    if (p >= TEXD * TEXD) return;

    float x = uv[p];
    float y = uv[(TEXD * TEXD) + p];

    float ix = ((x + 1.f) * (float)TEXP - 1.f) * 0.5f;
    float iy = ((y + 1.f) * (float)TEXP - 1.f) * 0.5f;
    ix = fminf(fmaxf(ix, 0.f), (float)(TEXP - 1));
    iy = fminf(fmaxf(iy, 0.f), (float)(TEXP - 1));

    float fx0 = floorf(ix), fy0 = floorf(iy);
    float wx = ix - fx0, wy = iy - fy0;
    int xi0 = (int)fx0, yi0 = (int)fy0;
    int xi1 = min(xi0 + 1, TEXP - 1);
    int yi1 = min(yi0 + 1, TEXP - 1);

    const float4* t00 = (const float4*)&g_tex[(yi0 * TEXP + xi0) * OUTC];
    const float4* t01 = (const float4*)&g_tex[(yi0 * TEXP + xi1) * OUTC];
    const float4* t10 = (const float4*)&g_tex[(yi1 * TEXP + xi0) * OUTC];
    const float4* t11 = (const float4*)&g_tex[(yi1 * TEXP + xi1) * OUTC];

    float w00 = (1.f - wx) * (1.f - wy);
    float w01 = wx * (1.f - wy);
    float w10 = (1.f - wx) * wy;
    float w11 = wx * wy;

    #pragma unroll
    for (int v = 0; v < 4; ++v) {
        float4 a = t00[v], b = t01[v], cc = t10[v], dd = t11[v];
        float r0 = a.x * w00 + b.x * w01 + cc.x * w10 + dd.x * w11;
        float r1 = a.y * w00 + b.y * w01 + cc.y * w10 + dd.y * w11;
        float r2 = a.z * w00 + b.z * w01 + cc.z * w10 + dd.z * w11;
        float r3 = a.w * w00 + b.w * w01 + cc.w * w10 + dd.w * w11;
        out[(v * 4 + 0) * (TEXD * TEXD) + p] = r0;
        out[(v * 4 + 1) * (TEXD * TEXD) + p] = r1;
        out[(v * 4 + 2) * (TEXD * TEXD) + p] = r2;
        out[(v * 4 + 3) * (TEXD * TEXD) + p] = r3;
    }
}

// ---------------------------------------------------------------------------
// Inputs (metadata order): expressions, audio_features(unused), uv_inputs,
// data, W1, b1, W2, b2, W3, b3
// ---------------------------------------------------------------------------
extern "C" void kernel_launch(void* const* d_in, const int* in_sizes, int n_in,
                              void* d_out, int out_size)
{
    const float* expr = (const float*)d_in[0];
    const float* uv   = (const float*)d_in[2];
    const float* data = (const float*)d_in[3];
    const float* W1   = (const float*)d_in[4];
    const float* b1   = (const float*)d_in[5];
    const float* W2   = (const float*)d_in[6];
    const float* b2   = (const float*)d_in[7];
    const float* W3   = (const float*)d_in[8];
    const float* b3   = (const float*)d_in[9];
    float* out = (float*)d_out;

    mlp_kernel<<<1, 256>>>(expr, W1, b1, W2, b2, W3, b3);

    dim3 cgrid((TEXP + TILE - 1) / TILE, (TEXP + TILE - 1) / TILE);  // 33 x 33
    conv_kernel<<<cgrid, 256>>>(data);

    sample_kernel<<<(TEXD * TEXD + 255) / 256, 256>>>(uv, out);
}

// round 4
// speedup vs baseline: 2.5885x; 2.5885x over previous
#include <cuda_runtime.h>

#define TEXD   1024
#define TEXP   1025          // conv output spatial dim (1024 + 4 - 4 + 1)
#define OUTC   16
#define INC    32
#define TILE   32
#define HALO   35            // TILE + 3
#define CHUNK  8             // input channels per smem chunk

typedef unsigned long long u64;

// Scratch (device globals — no allocation allowed)
__device__ float g_filt[INC * 16 * OUTC];          // [i][ky*4+kx][o]
__device__ float g_h2[64];                         // MLP hidden 2
__device__ float g_tex[TEXP * TEXP * OUTC];        // [y][x][o]  (channel-last)

// ---------------- packed f32x2 helpers (Blackwell FFMA2) -------------------
__device__ __forceinline__ u64 pack2(float lo, float hi) {
    u64 r; asm("mov.b64 %0, {%1, %2};" : "=l"(r) : "f"(lo), "f"(hi)); return r;
}
__device__ __forceinline__ void fma2(u64& d, u64 a, u64 b) {
    asm("fma.rn.f32x2 %0, %1, %2, %3;" : "=l"(d) : "l"(a), "l"(b), "l"(d));
}

// ---------------------------------------------------------------------------
// Kernel 1a: MLP layers 1-2 (tiny, 1 block) -> g_h2
// ---------------------------------------------------------------------------
__global__ void mlp12_kernel(const float* __restrict__ expr,
                             const float* __restrict__ W1, const float* __restrict__ b1,
                             const float* __restrict__ W2, const float* __restrict__ b2)
{
    __shared__ float sx[76];
    __shared__ float h1[128];
    const int tid = threadIdx.x;

    if (tid < 76) sx[tid] = expr[tid];
    __syncthreads();

    if (tid < 128) {
        float a = b1[tid];
        const float* w = W1 + tid * 76;
        #pragma unroll 4
        for (int k = 0; k < 76; ++k) a = fmaf(w[k], sx[k], a);
        h1[tid] = (a >= 0.f) ? a : 0.02f * a;
    }
    __syncthreads();

    if (tid < 64) {
        float a = b2[tid];
        const float* w = W2 + tid * 128;
        #pragma unroll 4
        for (int k = 0; k < 128; ++k) a = fmaf(w[k], h1[k], a);
        g_h2[tid] = (a >= 0.f) ? a : 0.02f * a;
    }
}

// ---------------------------------------------------------------------------
// Kernel 1b: MLP layer 3 (64 -> 8192), warp per output, coalesced W3 reads.
// grid = 1024 blocks x 256 threads (8 warps) -> 8192 outputs.
// ---------------------------------------------------------------------------
__global__ void filt_kernel(const float* __restrict__ W3, const float* __restrict__ b3)
{
    const int lane = threadIdx.x & 31;
    const int warp = threadIdx.x >> 5;
    const int m    = blockIdx.x * 8 + warp;          // output index 0..8191

    const float* w = W3 + m * 64;
    float v = w[lane]      * g_h2[lane]
            + w[lane + 32] * g_h2[lane + 32];
    #pragma unroll
    for (int s = 16; s > 0; s >>= 1)
        v += __shfl_xor_sync(0xFFFFFFFFu, v, s);

    if (lane == 0) {
        float a = tanhf(v + b3[m]);
        int o = m >> 9;          // m / 512
        int r = m & 511;         // i*16 + t
        g_filt[r * OUTC + o] = a;
    }
}

// ---------------------------------------------------------------------------
// Kernel 2: conv 32ch -> 16ch, 4x4, pad 2, output 1025x1025 channel-last.
// FFMA2 inner loop: 8 packed accumulators per pixel (16 out channels).
// ---------------------------------------------------------------------------
__global__ void __launch_bounds__(256, 2)
conv_kernel(const float* __restrict__ data)
{
    __shared__ float sdata[CHUNK * HALO * HALO];   // 38.3 KB
    __shared__ float sfilt[CHUNK * 16 * OUTC];     //  8.0 KB

    const int tid = threadIdx.x;
    const int q   = tid & 7;        // x-quad 0..7
    const int ty  = tid >> 3;       // row 0..31
    const int x0  = blockIdx.x * TILE;
    const int y0  = blockIdx.y * TILE;

    u64 acc[4][8];
    #pragma unroll
    for (int p = 0; p < 4; ++p)
        #pragma unroll
        for (int j = 0; j < 8; ++j) acc[p][j] = 0ULL;

    for (int c = 0; c < INC / CHUNK; ++c) {
        // ---- load filter chunk ----
        #pragma unroll
        for (int j = tid; j < CHUNK * 16 * OUTC; j += 256)
            sfilt[j] = g_filt[c * (CHUNK * 16 * OUTC) + j];

        // ---- load data chunk (zero-padded halo) ----
        for (int idx = tid; idx < CHUNK * HALO * HALO; idx += 256) {
            int i   = idx / (HALO * HALO);
            int rem = idx - i * (HALO * HALO);
            int r   = rem / HALO;
            int cc  = rem - r * HALO;
            int gy  = y0 - 2 + r;
            int gx  = x0 - 2 + cc;
            float v = 0.f;
            if ((unsigned)gy < 1024u && (unsigned)gx < 1024u) {
                int ci = (c << 3) + i;
                v = data[(ci << 20) + (gy << 10) + gx];
            }
            sdata[idx] = v;
        }
        __syncthreads();

        #pragma unroll 1
        for (int i = 0; i < CHUNK; ++i) {
            #pragma unroll
            for (int ky = 0; ky < 4; ++ky) {
                const float* drow = &sdata[i * (HALO * HALO) + (ty + ky) * HALO + 4 * q];
                float d[7];
                #pragma unroll
                for (int t = 0; t < 7; ++t) d[t] = drow[t];

                #pragma unroll
                for (int kx = 0; kx < 4; ++kx) {
                    const u64* w2 = (const u64*)&sfilt[((i * 4 + ky) * 4 + kx) * OUTC];
                    u64 wp[8];
                    #pragma unroll
                    for (int j = 0; j < 8; ++j) wp[j] = w2[j];

                    #pragma unroll
                    for (int p = 0; p < 4; ++p) {
                        u64 dv2 = pack2(d[p + kx], d[p + kx]);
                        #pragma unroll
                        for (int j = 0; j < 8; ++j)
                            fma2(acc[p][j], dv2, wp[j]);
                    }
                }
            }
        }
        __syncthreads();
    }

    // ---- store channel-last (pairs are consecutive channels) ----
    const int oy = y0 + ty;
    if (oy < TEXP) {
        #pragma unroll
        for (int p = 0; p < 4; ++p) {
            int ox = x0 + 4 * q + p;
            if (ox < TEXP) {
                ulonglong2* dst = (ulonglong2*)&g_tex[(oy * TEXP + ox) * OUTC];
                #pragma unroll
                for (int j = 0; j < 4; ++j)
                    dst[j] = make_ulonglong2(acc[p][2 * j], acc[p][2 * j + 1]);
            }
        }
    }
}

// ---------------------------------------------------------------------------
// Kernel 3: bilinear grid sample (border padding, align_corners=False)
// ---------------------------------------------------------------------------
__global__ void sample_kernel(const float* __restrict__ uv, float* __restrict__ out)
{
    int p = blockIdx.x * blockDim.x + threadIdx.x;
    if (p >= TEXD * TEXD) return;

    float x = uv[p];
    float y = uv[(TEXD * TEXD) + p];

    float ix = ((x + 1.f) * (float)TEXP - 1.f) * 0.5f;
    float iy = ((y + 1.f) * (float)TEXP - 1.f) * 0.5f;
    ix = fminf(fmaxf(ix, 0.f), (float)(TEXP - 1));
    iy = fminf(fmaxf(iy, 0.f), (float)(TEXP - 1));

    float fx0 = floorf(ix), fy0 = floorf(iy);
    float wx = ix - fx0, wy = iy - fy0;
    int xi0 = (int)fx0, yi0 = (int)fy0;
    int xi1 = min(xi0 + 1, TEXP - 1);
    int yi1 = min(yi0 + 1, TEXP - 1);

    const float4* t00 = (const float4*)&g_tex[(yi0 * TEXP + xi0) * OUTC];
    const float4* t01 = (const float4*)&g_tex[(yi0 * TEXP + xi1) * OUTC];
    const float4* t10 = (const float4*)&g_tex[(yi1 * TEXP + xi0) * OUTC];
    const float4* t11 = (const float4*)&g_tex[(yi1 * TEXP + xi1) * OUTC];

    float w00 = (1.f - wx) * (1.f - wy);
    float w01 = wx * (1.f - wy);
    float w10 = (1.f - wx) * wy;
    float w11 = wx * wy;

    #pragma unroll
    for (int v = 0; v < 4; ++v) {
        float4 a = t00[v], b = t01[v], cc = t10[v], dd = t11[v];
        float r0 = a.x * w00 + b.x * w01 + cc.x * w10 + dd.x * w11;
        float r1 = a.y * w00 + b.y * w01 + cc.y * w10 + dd.y * w11;
        float r2 = a.z * w00 + b.z * w01 + cc.z * w10 + dd.z * w11;
        float r3 = a.w * w00 + b.w * w01 + cc.w * w10 + dd.w * w11;
        out[(v * 4 + 0) * (TEXD * TEXD) + p] = r0;
        out[(v * 4 + 1) * (TEXD * TEXD) + p] = r1;
        out[(v * 4 + 2) * (TEXD * TEXD) + p] = r2;
        out[(v * 4 + 3) * (TEXD * TEXD) + p] = r3;
    }
}

// ---------------------------------------------------------------------------
// Inputs (metadata order): expressions, audio_features(unused), uv_inputs,
// data, W1, b1, W2, b2, W3, b3
// ---------------------------------------------------------------------------
extern "C" void kernel_launch(void* const* d_in, const int* in_sizes, int n_in,
                              void* d_out, int out_size)
{
    const float* expr = (const float*)d_in[0];
    const float* uv   = (const float*)d_in[2];
    const float* data = (const float*)d_in[3];
    const float* W1   = (const float*)d_in[4];
    const float* b1   = (const float*)d_in[5];
    const float* W2   = (const float*)d_in[6];
    const float* b2   = (const float*)d_in[7];
    const float* W3   = (const float*)d_in[8];
    const float* b3   = (const float*)d_in[9];
    float* out = (float*)d_out;

    mlp12_kernel<<<1, 128>>>(expr, W1, b1, W2, b2);
    filt_kernel<<<1024, 256>>>(W3, b3);

    dim3 cgrid((TEXP + TILE - 1) / TILE, (TEXP + TILE - 1) / TILE);  // 33 x 33
    conv_kernel<<<cgrid, 256>>>(data);

    sample_kernel<<<(TEXD * TEXD + 255) / 256, 256>>>(uv, out);
}